// round 17
// baseline (speedup 1.0000x reference)
#include <cuda_runtime.h>

#define LBL 32
#define WPB 8
#define ESTR 36   // staging/expTlo stride: (4*tg+tq) bank map, conflict-free

typedef unsigned int u32;

// Static device scratch (allocation-free). Distinct buffer per phase.
// Score buffers use ROTATED rows: label l of row n at column (l + 8*(n%4))%32.
__device__ __align__(16) float g_bufA[16384 * LBL];
__device__ __align__(16) float g_bufB[2048 * LBL];
__device__ __align__(16) float g_bufC[256 * LBL];
__device__ __align__(16) float g_bufD[32 * LBL];

// Grid barrier state (re-entrant across graph replays).
__device__ unsigned g_bar_count = 0;
__device__ unsigned g_bar_phase = 0;

__device__ __forceinline__ void grid_barrier(unsigned nblocks, unsigned& myphase) {
    __syncthreads();
    if (threadIdx.x == 0) {
        __threadfence();
        unsigned arr = atomicAdd(&g_bar_count, 1u);
        if (arr == nblocks - 1u) {
            g_bar_count = 0;
            __threadfence();
            atomicAdd(&g_bar_phase, 1u);
        } else {
            while (*(volatile unsigned*)&g_bar_phase == myphase)
                __nanosleep(64);
        }
    }
    __syncthreads();
    myphase++;
}

// Warp max of f32 via monotone int map + redux.sync.max.s32.
__device__ __forceinline__ float warp_fmax1(float x) {
    int b = __float_as_int(x);
    int key = b ^ ((b >> 31) & 0x7fffffff);
    int r;
    asm("redux.sync.max.s32 %0, %1, 0xffffffff;" : "=r"(r) : "r"(key));
    return __int_as_float(r ^ ((r >> 31) & 0x7fffffff));
}

__device__ __forceinline__ u32 f2tf32(float x) {
    u32 h; asm("cvt.rna.tf32.f32 %0, %1;" : "=r"(h) : "f"(x)); return h;
}

// D(16x8) += A(16x8,tf32,row) @ B(8x8,tf32,col), fp32 accumulate.
__device__ __forceinline__ void mma_acc(float c[4], const u32 a[4], u32 b0, u32 b1) {
    asm("mma.sync.aligned.m16n8k8.row.col.f32.tf32.tf32.f32 "
        "{%0,%1,%2,%3}, {%4,%5,%6,%7}, {%8,%9}, {%0,%1,%2,%3};"
        : "+f"(c[0]), "+f"(c[1]), "+f"(c[2]), "+f"(c[3])
        : "r"(a[0]), "r"(a[1]), "r"(a[2]), "r"(a[3]), "r"(b0), "r"(b1));
}

// ---- cp.async helpers -----------------------------------------------------
__device__ __forceinline__ void cp16(float* smem_dst, const float* gmem_src) {
    unsigned sa = (unsigned)__cvta_generic_to_shared(smem_dst);
    asm volatile("cp.async.cg.shared.global [%0], [%1], 16;"
                 :: "r"(sa), "l"(gmem_src));
}
#define CP_COMMIT() asm volatile("cp.async.commit_group;")
#define CP_WAIT0()  asm volatile("cp.async.wait_group 0;" ::: "memory")

// Prefetch one 32-node slab: 64 child rows -> cb, 32 em1 rows -> eb.
__device__ __forceinline__ void prefetch_slab32(
    float* __restrict__ cb, float* __restrict__ eb,
    const float* __restrict__ child, const float* __restrict__ em1,
    int s, int tid)
{
    const float* sc = child + (size_t)(s * 64) * LBL;   // 512 x 16B
    cp16(cb + (size_t)tid * 4, sc + (size_t)tid * 4);
    cp16(cb + (size_t)(tid + 256) * 4, sc + (size_t)(tid + 256) * 4);
    const float* se = em1 + (size_t)(s * 32) * LBL;     // 256 x 16B
    cp16(eb + (size_t)tid * 4, se + (size_t)tid * 4);
}

// ---------------------------------------------------------------------------
// Batch of 4 tree nodes per warp via tensor cores (R12 math, verified).
// Thread t owns node (t%4) and labels (t/4)+8k in res[k].
// 3-term tf32x2 split (AhBh + AhBl + AlBh); AH in regs, AL (tf32 bits) in
// shared TL[32*36]. Split accumulators (a: s4<2, b: s4>=2) halve the HMMA
// dependency chain. Staging stg[vec][label] is label-indexed, conflict-free.
// ---------------------------------------------------------------------------
template<bool ROT_IN>
__device__ __forceinline__ void batch4(
    const float* __restrict__ child, int crow0,   // child rows crow0..crow0+7
    const float* __restrict__ em,    int erow0,   // emission rows erow0..+3
    int lane, float* __restrict__ stg,            // 8*ESTR floats per warp
    const u32 (&AH)[2][4][4], const u32* __restrict__ TL,
    float res[4])
{
    const int tq = lane & 3, tg = lane >> 2;

    float mm0, mm1, mm2, mm3;
    #pragma unroll
    for (int i = 0; i < 4; i++) {
        int rl = crow0 + 2 * i, rr = rl + 1;
        int il = ROT_IN ? ((lane + 8 * rl) & 31) : lane;
        int ir = ROT_IN ? ((lane + 8 * rr) & 31) : lane;
        float lv = child[rl * LBL + il];
        float rv = child[rr * LBL + ir];
        float ml = warp_fmax1(lv);
        float mr = warp_fmax1(rv);
        stg[(2 * i) * ESTR + lane]     = __expf(lv - ml);   // E^T[vec][label]
        stg[(2 * i + 1) * ESTR + lane] = __expf(rv - mr);
        float sv = ml + mr;
        if (i == 0) mm0 = sv; else if (i == 1) mm1 = sv;
        else if (i == 2) mm2 = sv; else mm3 = sv;
    }
    float emv[4];
    #pragma unroll
    for (int k = 0; k < 4; k++)
        emv[k] = em[(size_t)(erow0 + tq) * LBL + tg + 8 * k];
    __syncwarp();

    float c0a[4] = {0,0,0,0}, c0b[4] = {0,0,0,0};
    float c1a[4] = {0,0,0,0}, c1b[4] = {0,0,0,0};
    #pragma unroll
    for (int s4 = 0; s4 < 4; s4++) {
        float* cc0 = (s4 < 2) ? c0a : c0b;
        float* cc1 = (s4 < 2) ? c1a : c1b;
        float b0f = stg[tg * ESTR + tq + 8 * s4];
        float b1f = stg[tg * ESTR + tq + 4 + 8 * s4];
        u32 b0h = f2tf32(b0f), b1h = f2tf32(b1f);
        u32 b0l = f2tf32(b0f - __uint_as_float(b0h));
        u32 b1l = f2tf32(b1f - __uint_as_float(b1h));
        mma_acc(cc0, AH[0][s4], b0h, b1h);
        mma_acc(cc1, AH[1][s4], b0h, b1h);
        mma_acc(cc0, AH[0][s4], b0l, b1l);
        mma_acc(cc1, AH[1][s4], b0l, b1l);
        int ca = tq + 8 * s4, cb2 = ca + 4;
        u32 al[4];
        al[0] = TL[(tg)      * ESTR + ca];
        al[1] = TL[(tg + 8)  * ESTR + ca];
        al[2] = TL[(tg)      * ESTR + cb2];
        al[3] = TL[(tg + 8)  * ESTR + cb2];
        mma_acc(cc0, al, b0h, b1h);
        al[0] = TL[(tg + 16) * ESTR + ca];
        al[1] = TL[(tg + 24) * ESTR + ca];
        al[2] = TL[(tg + 16) * ESTR + cb2];
        al[3] = TL[(tg + 24) * ESTR + cb2];
        mma_acc(cc1, al, b0h, b1h);
    }
    __syncwarp();   // stg reusable by next call

    float mmq = (tq & 2) ? ((tq & 1) ? mm3 : mm2) : ((tq & 1) ? mm1 : mm0);
    res[0] = emv[0] + mmq + __logf((c0a[0] + c0b[0]) * (c0a[1] + c0b[1]));
    res[1] = emv[1] + mmq + __logf((c0a[2] + c0b[2]) * (c0a[3] + c0b[3]));
    res[2] = emv[2] + mmq + __logf((c1a[0] + c1b[0]) * (c1a[1] + c1b[1]));
    res[3] = emv[3] + mmq + __logf((c1a[2] + c1b[2]) * (c1a[3] + c1b[3]));
}

// ---------------------------------------------------------------------------
// Persistent kernel: all levels, one launch, grid barrier between fused-3
// groups. Slab = 32 nodes at level V -> 16 -> 8 via rotated smem rows.
// ---------------------------------------------------------------------------
__global__ void __launch_bounds__(WPB * 32, 3)
persistent_kernel(const float* __restrict__ emissions,
                  const float* __restrict__ trans,
                  float* __restrict__ d_out,
                  int n_leaves)
{
    __shared__ __align__(16) float s1[32 * LBL];
    __shared__ __align__(16) float s2[16 * LBL];
    __shared__ __align__(16) float stg[WPB][8 * ESTR];
    __shared__ __align__(16) float cbuf[2][64 * LBL];
    __shared__ __align__(16) float ebuf[2][32 * LBL];
    __shared__ __align__(16) u32   TLs[32 * ESTR];     // expT-lo, tf32 bits

    int tid  = threadIdx.x;
    int lane = tid & 31;
    int w    = tid >> 5;
    const int tq = lane & 3, tg = lane >> 2;
    unsigned nblocks = gridDim.x;
    unsigned myphase = *(volatile unsigned*)&g_bar_phase;

    // AH fragments (tf32-hi of expT) in registers, 32 regs.
    u32 AH[2][4][4];
    #pragma unroll
    for (int r = 0; r < 2; r++) {
        #pragma unroll
        for (int s = 0; s < 4; s++) {
            int r0 = tg + 16 * r, r1 = r0 + 8;
            int ca = tq + 8 * s,  cb = ca + 4;
            AH[r][s][0] = f2tf32(__expf(trans[r0 * LBL + ca]));
            AH[r][s][1] = f2tf32(__expf(trans[r1 * LBL + ca]));
            AH[r][s][2] = f2tf32(__expf(trans[r0 * LBL + cb]));
            AH[r][s][3] = f2tf32(__expf(trans[r1 * LBL + cb]));
        }
    }
    // expT-lo matrix -> shared, pre-converted to tf32 bit patterns.
    for (int i = tid; i < 1024; i += WPB * 32) {
        int row = i >> 5, col = i & 31;
        float v = __expf(trans[i]);
        u32 h = f2tf32(v);
        TLs[row * ESTR + col] = f2tf32(v - __uint_as_float(h));
    }
    __syncthreads();

    float* bufs[4] = { g_bufA, g_bufB, g_bufC, g_bufD };
    const float* child = emissions + (size_t)(n_leaves - 1) * LBL;  // unrotated

    int V = n_leaves / 2;
    int gi = 0;
    while (V >= 128) {
        float* out = bufs[gi];
        const float* em1 = emissions + (size_t)(V - 1) * LBL;
        const float* em2 = emissions + (size_t)(V / 2 - 1) * LBL;
        const float* em3 = emissions + (size_t)(V / 4 - 1) * LBL;
        int nslabs = V / 32;

        int s = blockIdx.x;
        int idx = 0;
        if (s < nslabs)
            prefetch_slab32(cbuf[0], ebuf[0], child, em1, s, tid);
        CP_COMMIT();

        for (; s < nslabs; s += nblocks) {
            CP_WAIT0();          // slab s landed; prior slab fully consumed
            __syncthreads();

            int sn = s + nblocks;
            if (sn < nslabs)
                prefetch_slab32(cbuf[idx ^ 1], ebuf[idx ^ 1], child, em1, sn, tid);
            CP_COMMIT();

            const float* cb = cbuf[idx];
            const float* eb = ebuf[idx];
            float res[4];

            // ---- Stage 1: 32 nodes, 8 warps x 4. Children in cbuf (smem).
            if (gi == 0)
                batch4<false>(cb, 8 * w, eb, 4 * w, lane, stg[w], AH, TLs, res);
            else
                batch4<true >(cb, 8 * w, eb, 4 * w, lane, stg[w], AH, TLs, res);
            #pragma unroll
            for (int k = 0; k < 4; k++)
                s1[(4 * w + tq) * LBL + ((tg + 8 * k + 8 * tq) & 31)] = res[k];
            __syncthreads();

            // ---- Stage 2: 16 nodes, warps 0-3; em2 direct from global.
            if (w < 4) {
                batch4<true>(s1, 8 * w, em2, s * 16 + 4 * w, lane, stg[w], AH, TLs, res);
                #pragma unroll
                for (int k = 0; k < 4; k++)
                    s2[(4 * w + tq) * LBL + ((tg + 8 * k + 8 * tq) & 31)] = res[k];
            }
            __syncthreads();

            // ---- Stage 3: 8 nodes, warps 0-1 -> global (rotated).
            if (w < 2) {
                batch4<true>(s2, 8 * w, em3, s * 8 + 4 * w, lane, stg[w], AH, TLs, res);
                int row = s * 8 + 4 * w + tq;
                #pragma unroll
                for (int k = 0; k < 4; k++)
                    out[(size_t)row * LBL + ((tg + 8 * k + 8 * (row & 3)) & 31)] = res[k];
            }
            // top-of-loop __syncthreads covers s1/s2/cbuf reuse
            idx ^= 1;
        }

        CP_WAIT0();
        grid_barrier(nblocks, myphase);
        child = out;
        V >>= 3;
        gi++;
    }

    // ---- Tail: levels V..1 (V=16), block 0 only. Pad nodes read in-bounds
    // stale rows (finite) and are not stored.
    if (blockIdx.x == 0) {
        const float* c = child;   // g_bufD, rotated
        float* o = s2;
        for (int v = V; v >= 1; v >>= 1) {
            const float* em = emissions + (size_t)(v - 1) * LBL;
            int aw = (v >= 4) ? (v / 4) : 1;
            if (w < aw) {
                float res[4];
                batch4<true>(c, 8 * w, em, 4 * w, lane, stg[w], AH, TLs, res);
                int valid = v - 4 * w; if (valid > 4) valid = 4;
                if (v == 1) {
                    if (tq == 0) {
                        #pragma unroll
                        for (int k = 0; k < 4; k++)
                            d_out[tg + 8 * k] = res[k];
                    }
                } else {
                    #pragma unroll
                    for (int k = 0; k < 4; k++)
                        if (tq < valid)
                            o[(4 * w + tq) * LBL + ((tg + 8 * k + 8 * tq) & 31)] = res[k];
                }
            }
            __syncthreads();
            c = o;
            o = (o == s2) ? s1 : s2;
        }
    }
}

// ---------------------------------------------------------------------------
// One graph node. Grid sized so ALL blocks are simultaneously resident.
// ---------------------------------------------------------------------------
extern "C" void kernel_launch(void* const* d_in, const int* in_sizes, int n_in,
                              void* d_out, int out_size)
{
    const float* emissions = (const float*)d_in[0];
    const float* trans     = (const float*)d_in[1];
    float* out = (float*)d_out;

    int n_nodes  = in_sizes[0] / LBL;
    int n_leaves = (n_nodes + 1) / 2;

    static int grid = 0;
    if (grid == 0) {
        int dev = 0, sms = 0, perSM = 0;
        cudaGetDevice(&dev);
        cudaDeviceGetAttribute(&sms, cudaDevAttrMultiProcessorCount, dev);
        cudaOccupancyMaxActiveBlocksPerMultiprocessor(
            &perSM, persistent_kernel, WPB * 32, 0);
        if (perSM < 1) perSM = 1;
        grid = sms * perSM;
        int maxSlabs = (n_leaves / 2) / 32;
        if (grid > maxSlabs) grid = maxSlabs;
        if (grid < 1) grid = 1;
    }

    persistent_kernel<<<grid, WPB * 32>>>(emissions, trans, out, n_leaves);
}